// round 7
// baseline (speedup 1.0000x reference)
#include <cuda_runtime.h>
#include <cuda_bf16.h>
#include <cstdint>

#define T_LEN 4000
#define HALF  2000
#define BLOCK 128
#define SEG   16
#define NSEG  125
#define GRID  1776
#define HALO  32
#define P16(i) ((i) + (((i) >> 5) << 2))
#define BUFSZ 2284   // P16(HALO + HALF - 1) + 1

__device__ __forceinline__ float fast_exp2(float x) {
    float y; asm("ex2.approx.ftz.f32 %0, %1;" : "=f"(y) : "f"(x)); return y;
}
__device__ __forceinline__ float fast_log2(float x) {
    float y; asm("lg2.approx.ftz.f32 %0, %1;" : "=f"(y) : "f"(x)); return y;
}
__device__ __forceinline__ float fast_sqrt(float x) {
    float y; asm("sqrt.approx.ftz.f32 %0, %1;" : "=f"(y) : "f"(x)); return y;
}
__device__ __forceinline__ void cp_async16(uint32_t dst, const float* src) {
    asm volatile("cp.async.cg.shared.global [%0], [%1], 16;\n" :: "r"(dst), "l"(src));
}
#define CP_COMMIT() asm volatile("cp.async.commit_group;\n" ::: "memory")
#define CP_WAIT1()  asm volatile("cp.async.wait_group 1;\n" ::: "memory")

#define S_C   (512.0f / 1323.0f)
#define OMS_C (1.0f - 512.0f / 1323.0f)

struct Params { float delta, r, dr, nalpha; bool rhalf; };

__device__ __forceinline__ float pcen_elem(float xv, float M, const Params& p) {
    float L    = fast_log2(1e-6f + M);
    float sinv = fast_exp2(p.nalpha * L);
    float bse  = fmaf(xv, sinv, p.delta);            // > 0
    return (p.rhalf ? fast_sqrt(bse)
                    : fast_exp2(p.r * fast_log2(bse))) - p.dr;
}

__device__ __forceinline__ float horner4(float M, float4 v) {
    M = OMS_C * M + S_C * v.x;
    M = OMS_C * M + S_C * v.y;
    M = OMS_C * M + S_C * v.z;
    M = OMS_C * M + S_C * v.w;
    return M;
}

// stage one half-row unit (u = 2*row + half) into smem buffer (async)
__device__ __forceinline__ void prefetch_unit(uint32_t sb, const float* __restrict__ x,
                                              int u, int tid) {
    const int row  = u >> 1;
    const int half = u & 1;
    const int nch  = half ? 508 : 500;           // half1 includes 32-float halo
    const int Ls   = half ? 0 : HALO;            // local start index
    const float* src = x + (size_t)row * T_LEN + (half ? (HALF - HALO) : 0);
    #pragma unroll
    for (int m = tid; m < nch; m += BLOCK) {
        int L = Ls + 4 * m;
        cp_async16(sb + 4u * (uint32_t)P16(L), src + 4 * m);
    }
}

__global__ __launch_bounds__(BLOCK) void pcen_kernel(
    const float* __restrict__ x,
    const float* __restrict__ alpha_p,
    const float* __restrict__ delta_p,
    const float* __restrict__ r_p,
    float* __restrict__ out,
    int units)
{
    __shared__ __align__(16) float bufs[2][BUFSZ];   // 2 x 9136 B

    const int bid = blockIdx.x;
    const int tid = threadIdx.x;
    if (bid >= units) return;

    uint32_t sbase[2];
    sbase[0] = (uint32_t)__cvta_generic_to_shared(bufs[0]);
    sbase[1] = (uint32_t)__cvta_generic_to_shared(bufs[1]);

    // scalar params
    Params p;
    {
        float alpha = fminf(fmaxf(alpha_p[0], 0.01f), 0.99f);
        p.delta  = fabsf(delta_p[0]) + 1e-6f;
        p.r      = fminf(fmaxf(r_p[0], 0.01f), 1.0f);
        p.rhalf  = (p.r == 0.5f);
        p.dr     = p.rhalf ? fast_sqrt(p.delta)
                           : fast_exp2(p.r * fast_log2(p.delta));
        p.nalpha = -alpha;
    }

    const bool act = tid < NSEG;
    const int  w0  = SEG * tid;          // local window start (= L0 - HALO)

    // prologue: prefetch first unit
    prefetch_unit(sbase[0], x, bid, tid);
    CP_COMMIT();

    int pb = 0;
    #pragma unroll 1
    for (int u = bid; u < units; u += GRID, pb ^= 1) {
        // prefetch next unit into the other buffer (empty group if none -> uniform wait)
        if (u + GRID < units)
            prefetch_unit(sbase[pb ^ 1], x, u + GRID, tid);
        CP_COMMIT();
        CP_WAIT1();                       // current unit staged
        __syncthreads();                  // BAR1: visible to all threads

        const float* __restrict__ buf = bufs[pb];
        const int row  = u >> 1;
        const int half = u & 1;

        // ---- window: reconstruct M just before t0 (no barrier needed: read-only) ----
        float M = 0.0f;
        if (act) {
            if (half || tid >= 2) {
                // uniform 32-tap Horner; half1 uses halo slot [0,32)
                #pragma unroll
                for (int g = 0; g < 8; g++) {
                    float4 v = *(const float4*)&buf[P16(w0 + 4 * g)];
                    M = horner4(M, v);
                }
            } else if (tid == 0) {
                M = buf[P16(HALO)];       // seed: step yields M[0] = x[0] exactly
            } else {                      // tid == 1, exact M[15]
                float4 v0 = *(const float4*)&buf[P16(HALO)];
                M = v0.x;
                M = OMS_C * M + S_C * v0.y;
                M = OMS_C * M + S_C * v0.z;
                M = OMS_C * M + S_C * v0.w;
                #pragma unroll
                for (int g = 1; g < 4; g++) {
                    float4 v = *(const float4*)&buf[P16(HALO + 4 * g)];
                    M = horner4(M, v);
                }
            }
        }

        // ---- compute 16 elems; results go straight to global (regs -> STG.128) ----
        if (act) {
            float* __restrict__ outp = out + (size_t)row * T_LEN + half * HALF + w0;
            #pragma unroll
            for (int q = 0; q < 4; q++) {
                float4 v = *(const float4*)&buf[P16(HALO + w0 + 4 * q)];
                float4 o;
                M = OMS_C * M + S_C * v.x;  o.x = pcen_elem(v.x, M, p);
                M = OMS_C * M + S_C * v.y;  o.y = pcen_elem(v.y, M, p);
                M = OMS_C * M + S_C * v.z;  o.z = pcen_elem(v.z, M, p);
                M = OMS_C * M + S_C * v.w;  o.w = pcen_elem(v.w, M, p);
                *(float4*)(outp + 4 * q) = o;
            }
        }
        __syncthreads();                  // BAR2: buf reads done -> safe to refill next iter
    }
}

extern "C" void kernel_launch(void* const* d_in, const int* in_sizes, int n_in,
                              void* d_out, int out_size) {
    const float* mel   = (const float*)d_in[0];
    const float* alpha = (const float*)d_in[1];
    const float* delta = (const float*)d_in[2];
    const float* r     = (const float*)d_in[3];
    float* out = (float*)d_out;

    int rows  = out_size / T_LEN;     // 16384
    int units = 2 * rows;             // 32768
    int grid  = units < GRID ? units : GRID;
    pcen_kernel<<<grid, BLOCK>>>(mel, alpha, delta, r, out, units);
}

// round 8
// speedup vs baseline: 1.3733x; 1.3733x over previous
#include <cuda_runtime.h>
#include <cuda_bf16.h>
#include <cstdint>

#define T_LEN 4000
#define HALF  2000
#define BLOCK 128
#define SEG   16
#define NSEG  125
#define HALO  32
#define P16(i) ((i) + (((i) >> 5) << 2))
#define BUFSZ 2284   // P16(HALO + HALF - 1) + 1  -> 9136 bytes

__device__ __forceinline__ float fast_exp2(float x) {
    float y; asm("ex2.approx.ftz.f32 %0, %1;" : "=f"(y) : "f"(x)); return y;
}
__device__ __forceinline__ float fast_log2(float x) {
    float y; asm("lg2.approx.ftz.f32 %0, %1;" : "=f"(y) : "f"(x)); return y;
}
__device__ __forceinline__ float fast_sqrt(float x) {
    float y; asm("sqrt.approx.ftz.f32 %0, %1;" : "=f"(y) : "f"(x)); return y;
}
__device__ __forceinline__ void cp_async16(uint32_t dst, const float* src) {
    asm volatile("cp.async.cg.shared.global [%0], [%1], 16;\n" :: "r"(dst), "l"(src));
}

#define S_C   (512.0f / 1323.0f)
#define OMS_C (1.0f - 512.0f / 1323.0f)

struct Params { float delta, r, dr, nalpha; bool rhalf; };

__device__ __forceinline__ float pcen_elem(float xv, float M, const Params& p) {
    float L    = fast_log2(1e-6f + M);
    float sinv = fast_exp2(p.nalpha * L);
    float bse  = fmaf(xv, sinv, p.delta);            // > 0
    return (p.rhalf ? fast_sqrt(bse)
                    : fast_exp2(p.r * fast_log2(bse))) - p.dr;
}

__device__ __forceinline__ float horner4(float M, float4 v) {
    M = OMS_C * M + S_C * v.x;
    M = OMS_C * M + S_C * v.y;
    M = OMS_C * M + S_C * v.z;
    M = OMS_C * M + S_C * v.w;
    return M;
}

__global__ __launch_bounds__(BLOCK) void pcen_kernel(
    const float* __restrict__ x,
    const float* __restrict__ alpha_p,
    const float* __restrict__ delta_p,
    const float* __restrict__ r_p,
    float* __restrict__ out)
{
    __shared__ __align__(16) float buf[BUFSZ];

    const int u    = blockIdx.x;        // unit = 2*row + half
    const int tid  = threadIdx.x;
    const int row  = u >> 1;
    const int half = u & 1;

    const uint32_t sb = (uint32_t)__cvta_generic_to_shared(buf);

    // ---- stage this half-row (half1 includes 32-float halo) via cp.async ----
    {
        const float* src = x + (size_t)row * T_LEN + (half ? (HALF - HALO) : 0);
        const int nch = half ? 508 : 500;
        const int Ls  = half ? 0 : HALO;
        #pragma unroll
        for (int m = tid; m < nch; m += BLOCK) {
            int L = Ls + 4 * m;
            cp_async16(sb + 4u * (uint32_t)P16(L), src + 4 * m);
        }
    }
    asm volatile("cp.async.commit_group;\n" ::: "memory");

    // scalar params (overlap with async loads)
    Params p;
    {
        float alpha = fminf(fmaxf(alpha_p[0], 0.01f), 0.99f);
        p.delta  = fabsf(delta_p[0]) + 1e-6f;
        p.r      = fminf(fmaxf(r_p[0], 0.01f), 1.0f);
        p.rhalf  = (p.r == 0.5f);
        p.dr     = p.rhalf ? fast_sqrt(p.delta)
                           : fast_exp2(p.r * fast_log2(p.delta));
        p.nalpha = -alpha;
    }

    asm volatile("cp.async.wait_group 0;\n" ::: "memory");
    __syncthreads();                    // BAR1: data staged & visible

    const bool act = tid < NSEG;
    const int  w0  = SEG * tid;         // local window start (= local out - HALO)

    // ---- window: reconstruct M[t0-1] (32-tap Horner; exact at row start) ----
    float M = 0.0f;
    if (act) {
        if (half || tid >= 2) {
            #pragma unroll
            for (int g = 0; g < 8; g++) {
                float4 v = *(const float4*)&buf[P16(w0 + 4 * g)];
                M = horner4(M, v);
            }
        } else if (tid == 0) {
            M = buf[P16(HALO)];         // seed so first step gives M[0]=x[0]
        } else {                        // tid == 1: exact M[15]
            float4 v0 = *(const float4*)&buf[P16(HALO)];
            M = v0.x;
            M = OMS_C * M + S_C * v0.y;
            M = OMS_C * M + S_C * v0.z;
            M = OMS_C * M + S_C * v0.w;
            #pragma unroll
            for (int g = 1; g < 4; g++) {
                float4 v = *(const float4*)&buf[P16(HALO + 4 * g)];
                M = horner4(M, v);
            }
        }
    }
    __syncthreads();                    // BAR2: window reads done (in-place write next)

    // ---- compute 16 elems in place ----
    if (act) {
        #pragma unroll
        for (int q = 0; q < 4; q++) {
            float4 v = *(const float4*)&buf[P16(HALO + w0 + 4 * q)];
            float4 o;
            M = OMS_C * M + S_C * v.x;  o.x = pcen_elem(v.x, M, p);
            M = OMS_C * M + S_C * v.y;  o.y = pcen_elem(v.y, M, p);
            M = OMS_C * M + S_C * v.z;  o.z = pcen_elem(v.z, M, p);
            M = OMS_C * M + S_C * v.w;  o.w = pcen_elem(v.w, M, p);
            *(float4*)&buf[P16(HALO + w0 + 4 * q)] = o;
        }
    }
    __syncthreads();                    // BAR3: results ready

    // ---- coalesced writeback ----
    {
        float* __restrict__ outr = out + (size_t)row * T_LEN + half * HALF;
        #pragma unroll
        for (int i = tid; i < 500; i += BLOCK) {
            float4 v = *(const float4*)&buf[P16(HALO + 4 * i)];
            *(float4*)(outr + 4 * i) = v;
        }
    }
}

extern "C" void kernel_launch(void* const* d_in, const int* in_sizes, int n_in,
                              void* d_out, int out_size) {
    const float* mel   = (const float*)d_in[0];
    const float* alpha = (const float*)d_in[1];
    const float* delta = (const float*)d_in[2];
    const float* r     = (const float*)d_in[3];
    float* out = (float*)d_out;

    int rows = out_size / T_LEN;       // 16384
    pcen_kernel<<<2 * rows, BLOCK>>>(mel, alpha, delta, r, out);
}